// round 13
// baseline (speedup 1.0000x reference)
#include <cuda_runtime.h>
#include <stdint.h>

// Problem constants (fixed shapes)
#define N_A   500000
#define N_B   500000
#define NE    1000000
#define HID   64
#define NOUT  32

// ---------------- scratch (device globals: allocation-free) ----------------
__device__ float g_agg_ab[N_B];            // layer-1 scalar aggregates
__device__ float g_agg_ba[N_A];
__device__ float g_agg_aa[N_A];
__device__ float g_ta_ab[(size_t)N_A * NOUT];   // ha @ Wrel2[0]  (src-transform for a->b)
__device__ float g_ta_aa[(size_t)N_A * NOUT];   // ha @ Wrel2[2]  (src-transform for a->a)
__device__ float g_tb_ba[(size_t)N_B * NOUT];   // hb @ Wrel2[1]  (src-transform for b->a)
__device__ int   g_is64;                   // edge-index dtype flag

// ---------------- dtype probe ----------------
// int64 little-endian indices < 2^31 => every odd 32-bit word is 0.
__global__ void probe_kernel(const unsigned* __restrict__ ei) {
    __shared__ unsigned s;
    if (threadIdx.x == 0) s = 0u;
    __syncthreads();
    unsigned v = 0u;
    for (int i = threadIdx.x; i < 2048; i += blockDim.x) v |= ei[2 * i + 1];
    atomicOr(&s, v);
    __syncthreads();
    if (threadIdx.x == 0) g_is64 = (s == 0u) ? 1 : 0;
}

__device__ __forceinline__ int ld_idx(const void* __restrict__ ei, int row, int i, int is64) {
    if (is64) return (int)((const unsigned*)ei)[(((size_t)row * NE) + i) * 2];   // low word
    return ((const int*)ei)[((size_t)row * NE) + i];
}

// ---------------- zero the scalar aggregates (needed every replay) ----------------
__global__ void zero_aggs() {
    int gid = blockIdx.x * blockDim.x + threadIdx.x;
    if (gid < N_B) g_agg_ab[gid] = 0.f;
    if (gid < N_A) { g_agg_ba[gid] = 0.f; g_agg_aa[gid] = 0.f; }
}

// ---------------- layer-1 edge kernel: scalar scatter-add ----------------
__global__ void l1_edge(const void* __restrict__ ei_ab,
                        const void* __restrict__ ei_ba,
                        const void* __restrict__ ei_aa,
                        const float* __restrict__ xa,
                        const float* __restrict__ xb) {
    int gid = blockIdx.x * blockDim.x + threadIdx.x;
    if (gid >= 3 * NE) return;
    int is64 = g_is64;
    int t = gid / NE;
    int e = gid - t * NE;
    if (t == 0) {
        int s = ld_idx(ei_ab, 0, e, is64), d = ld_idx(ei_ab, 1, e, is64);
        atomicAdd(&g_agg_ab[d], xa[s]);                 // a -> b gathers x_a
    } else if (t == 1) {
        int s = ld_idx(ei_ba, 0, e, is64), d = ld_idx(ei_ba, 1, e, is64);
        atomicAdd(&g_agg_ba[d], xb[s]);                 // b -> a gathers x_b
    } else {
        int s = ld_idx(ei_aa, 0, e, is64), d = ld_idx(ei_aa, 1, e, is64);
        atomicAdd(&g_agg_aa[d], xa[s]);                 // a -> a gathers x_a
    }
}

// ---------------- packed f32x2 helpers ----------------
__device__ __forceinline__ unsigned long long pack2(float h) {
    unsigned long long r;
    asm("mov.b64 %0, {%1, %1};" : "=l"(r) : "f"(h));
    return r;
}
#define FMA2(acc, w, h) \
    asm("fma.rn.f32x2 %0, %1, %2, %0;" : "+l"(acc) : "l"(w), "l"(h))

#define RN 2   // nodes per thread (acc = 64 regs, leaves room for double buffer)

// one pipeline stage: compute hh for both nodes from hq, then 32 FMA2 on buf
#define NODEA_STAGE(buf, hq) do {                                              \
    unsigned long long hh0 = pack2(fmaxf(fmaf(s1[0], (hq).x,                   \
        fmaf(s2[0], (hq).y, fmaf(s3[0], (hq).z, (hq).w))), 0.f));              \
    unsigned long long hh1 = pack2(fmaxf(fmaf(s1[1], (hq).x,                   \
        fmaf(s2[1], (hq).y, fmaf(s3[1], (hq).z, (hq).w))), 0.f));              \
    _Pragma("unroll")                                                          \
    for (int m = 0; m < 8; m++) {                                              \
        FMA2(acc[0][2 * m],     (buf)[m].x, hh0);                              \
        FMA2(acc[0][2 * m + 1], (buf)[m].y, hh0);                              \
        FMA2(acc[1][2 * m],     (buf)[m].x, hh1);                              \
        FMA2(acc[1][2 * m + 1], (buf)[m].y, hh1);                              \
    }                                                                          \
} while (0)

#define NODEB_STAGE(buf, hq) do {                                              \
    unsigned long long hh0 = pack2(fmaxf(fmaf(s1[0], (hq).x,                   \
        fmaf(s3[0], (hq).y, (hq).z)), 0.f));                                   \
    unsigned long long hh1 = pack2(fmaxf(fmaf(s1[1], (hq).x,                   \
        fmaf(s3[1], (hq).y, (hq).z)), 0.f));                                   \
    _Pragma("unroll")                                                          \
    for (int m = 0; m < 8; m++) {                                              \
        FMA2(acc[0][2 * m],     (buf)[m].x, hh0);                              \
        FMA2(acc[0][2 * m + 1], (buf)[m].y, hh0);                              \
        FMA2(acc[1][2 * m],     (buf)[m].x, hh1);                              \
        FMA2(acc[1][2 * m + 1], (buf)[m].y, hh1);                              \
    }                                                                          \
} while (0)

// ================= node kernel for 'a' nodes =================
// 3 thread-groups (q) own 32 output cols each: q=0 -> g_ta_ab, q=1 -> g_ta_aa,
// q=2 -> out(+bias). RN=2 nodes/thread. Explicit double-buffered pipeline:
// weight row k+1 is loaded into the alternate register buffer BEFORE issuing
// row k's FMA2s, hiding the 29-cyc LDS latency inside the 64-cyc FMA2 burst.
__global__ void __launch_bounds__(192, 2)
node_a(const float* __restrict__ xa,
       const float* __restrict__ Wr1, const float* __restrict__ Wo1,
       const float* __restrict__ b1,
       const float* __restrict__ Wr2, const float* __restrict__ Wo2,
       const float* __restrict__ b2,
       float* __restrict__ out) {
    __shared__ __align__(16) float  sW[(HID + 2) * 96];  // +2 pad rows for tail prefetch
    __shared__ __align__(16) float4 sH[HID];             // {u, v, w, c} per k
    __shared__ __align__(16) float  sbias[NOUT];

    int tid = threadIdx.x;
    for (int idx = tid; idx < HID * 96; idx += blockDim.x) {
        int k = idx / 96, j = idx - k * 96;
        float v;
        if (j < 32)       v = Wr2[0 * HID * NOUT + k * NOUT + j];
        else if (j < 64)  v = Wr2[2 * HID * NOUT + k * NOUT + (j - 32)];
        else              v = Wo2[1 * HID * NOUT + k * NOUT + (j - 64)]
                            + Wo2[2 * HID * NOUT + k * NOUT + (j - 64)];
        sW[idx] = v;
    }
    for (int k = tid; k < HID; k += blockDim.x) {
        sH[k] = make_float4(Wr1[1 * HID + k],
                            Wr1[2 * HID + k],
                            Wo1[1 * HID + k] + Wo1[2 * HID + k],
                            b1[1 * HID + k] + b1[2 * HID + k]);
    }
    for (int j = tid; j < NOUT; j += blockDim.x)
        sbias[j] = b2[1 * NOUT + j] + b2[2 * NOUT + j];
    __syncthreads();

    int q  = tid >> 6;         // 0,1,2 : column slice / destination
    int ln = tid & 63;         // lane-group index
    int base = blockIdx.x * (64 * RN) + ln;

    int   nn[RN];
    float s1[RN], s2[RN], s3[RN];
#pragma unroll
    for (int i = 0; i < RN; i++) {
        int n = base + i * 64;
        nn[i] = n;
        bool ok = (n < N_A);
        int nc = ok ? n : 0;
        s1[i] = ok ? g_agg_ba[nc] : 0.f;
        s2[i] = ok ? g_agg_aa[nc] : 0.f;
        s3[i] = ok ? xa[nc] : 0.f;
    }

    unsigned long long acc[RN][16];
#pragma unroll
    for (int i = 0; i < RN; i++) {
        if (q == 2) {
            const unsigned long long* pb = (const unsigned long long*)sbias;
#pragma unroll
            for (int j = 0; j < 16; j++) acc[i][j] = pb[j];
        } else {
#pragma unroll
            for (int j = 0; j < 16; j++) acc[i][j] = 0ULL;
        }
    }

    // ---- double-buffered pipeline over k ----
    const ulonglong2* wrow = (const ulonglong2*)((const char*)sW + q * 32 * sizeof(float));
    ulonglong2 bufA[8], bufB[8];
    float4 hqA, hqB;
#pragma unroll
    for (int m = 0; m < 8; m++) bufA[m] = wrow[m];       // row 0
    hqA = sH[0];

#pragma unroll 1
    for (int k = 0; k < HID; k += 2) {
        const ulonglong2* w1 = wrow + 24;                // row k+1
#pragma unroll
        for (int m = 0; m < 8; m++) bufB[m] = w1[m];
        hqB = sH[k + 1];
        NODEA_STAGE(bufA, hqA);                          // consume row k

        wrow += 48;                                      // row k+2 (pad rows cover tail)
#pragma unroll
        for (int m = 0; m < 8; m++) bufA[m] = wrow[m];
        hqA = sH[(k + 2) & (HID - 1)];
        NODEA_STAGE(bufB, hqB);                          // consume row k+1
    }

    float* dst = (q == 0) ? g_ta_ab : (q == 1) ? g_ta_aa : out;
#pragma unroll
    for (int i = 0; i < RN; i++) {
        if (nn[i] < N_A) {
            ulonglong2* o = (ulonglong2*)(dst + (size_t)nn[i] * NOUT);
#pragma unroll
            for (int m = 0; m < 8; m++)
                o[m] = make_ulonglong2(acc[i][2 * m], acc[i][2 * m + 1]);
        }
    }
}

// ================= node kernel for 'b' nodes =================
// 128-thread blocks: 2 q-groups x 64 lanes; q=0 -> g_tb_ba; q=1 -> out(+bias).
// RN=2 nodes/thread, same explicit double-buffered pipeline.
__global__ void __launch_bounds__(128, 3)
node_b(const float* __restrict__ xb,
       const float* __restrict__ Wr1, const float* __restrict__ Wo1,
       const float* __restrict__ b1,
       const float* __restrict__ Wr2, const float* __restrict__ Wo2,
       const float* __restrict__ b2,
       float* __restrict__ out) {
    __shared__ __align__(16) float  sW[(HID + 2) * 64];  // +2 pad rows for tail prefetch
    __shared__ __align__(16) float4 sH[HID];             // {u, w, c, 0}
    __shared__ __align__(16) float  sbias[NOUT];

    int tid = threadIdx.x;
    for (int idx = tid; idx < HID * 64; idx += blockDim.x) {
        int k = idx / 64, j = idx - k * 64;
        float v;
        if (j < 32) v = Wr2[1 * HID * NOUT + k * NOUT + j];
        else        v = Wo2[0 * HID * NOUT + k * NOUT + (j - 32)];
        sW[idx] = v;
    }
    for (int k = tid; k < HID; k += blockDim.x) {
        sH[k] = make_float4(Wr1[0 * HID + k],
                            Wo1[0 * HID + k],
                            b1[0 * HID + k],
                            0.f);
    }
    for (int j = tid; j < NOUT; j += blockDim.x) sbias[j] = b2[0 * NOUT + j];
    __syncthreads();

    int q  = tid >> 6;         // 0,1 : column slice / destination
    int ln = tid & 63;         // lane-group index
    int base = blockIdx.x * (64 * RN) + ln;

    int   nn[RN];
    float s1[RN], s3[RN];
#pragma unroll
    for (int i = 0; i < RN; i++) {
        int n = base + i * 64;
        nn[i] = n;
        bool ok = (n < N_B);
        int nc = ok ? n : 0;
        s1[i] = ok ? g_agg_ab[nc] : 0.f;
        s3[i] = ok ? xb[nc] : 0.f;
    }

    unsigned long long acc[RN][16];
#pragma unroll
    for (int i = 0; i < RN; i++) {
        if (q == 1) {
            const unsigned long long* pb = (const unsigned long long*)sbias;
#pragma unroll
            for (int j = 0; j < 16; j++) acc[i][j] = pb[j];
        } else {
#pragma unroll
            for (int j = 0; j < 16; j++) acc[i][j] = 0ULL;
        }
    }

    // ---- double-buffered pipeline over k ----
    const ulonglong2* wrow = (const ulonglong2*)((const char*)sW + q * 32 * sizeof(float));
    ulonglong2 bufA[8], bufB[8];
    float4 hqA, hqB;
#pragma unroll
    for (int m = 0; m < 8; m++) bufA[m] = wrow[m];       // row 0
    hqA = sH[0];

#pragma unroll 1
    for (int k = 0; k < HID; k += 2) {
        const ulonglong2* w1 = wrow + 16;                // row k+1
#pragma unroll
        for (int m = 0; m < 8; m++) bufB[m] = w1[m];
        hqB = sH[k + 1];
        NODEB_STAGE(bufA, hqA);                          // consume row k

        wrow += 32;                                      // row k+2 (pad rows cover tail)
#pragma unroll
        for (int m = 0; m < 8; m++) bufA[m] = wrow[m];
        hqA = sH[(k + 2) & (HID - 1)];
        NODEB_STAGE(bufB, hqB);                          // consume row k+1
    }

    float* dst = (q == 0) ? g_tb_ba : (out + (size_t)N_A * NOUT);
#pragma unroll
    for (int i = 0; i < RN; i++) {
        if (nn[i] < N_B) {
            ulonglong2* o = (ulonglong2*)(dst + (size_t)nn[i] * NOUT);
#pragma unroll
            for (int m = 0; m < 8; m++)
                o[m] = make_ulonglong2(acc[i][2 * m], acc[i][2 * m + 1]);
        }
    }
}

// ---------------- layer-2 edge kernel: 32-wide row scatter via red.v4 ----------------
// one thread per (edge, float4-quadrant): 3*NE*8 threads  (known-good version)
__global__ void l2_edge(const void* __restrict__ ei_ab,
                        const void* __restrict__ ei_ba,
                        const void* __restrict__ ei_aa,
                        float* __restrict__ out) {
    long long gid = (long long)blockIdx.x * blockDim.x + threadIdx.x;
    if (gid >= 3LL * NE * 8) return;
    int is64 = g_is64;
    int t = (int)(gid / (NE * 8LL));
    long long r = gid - (long long)t * (NE * 8LL);
    int e = (int)(r >> 3);
    int q = (int)(r & 7);

    const void* ei = (t == 0) ? ei_ab : ((t == 1) ? ei_ba : ei_aa);
    int s = ld_idx(ei, 0, e, is64);
    int d = ld_idx(ei, 1, e, is64);

    const float* tsrc = (t == 0) ? g_ta_ab : ((t == 1) ? g_tb_ba : g_ta_aa);
    size_t drow = (t == 0) ? (size_t)(N_A + d) : (size_t)d;   // ab edges land in b-rows

    float4 v = *(const float4*)(tsrc + (size_t)s * NOUT + q * 4);
    float* p = out + drow * NOUT + q * 4;
    asm volatile("red.global.add.v4.f32 [%0], {%1, %2, %3, %4};"
                 :: "l"(p), "f"(v.x), "f"(v.y), "f"(v.z), "f"(v.w)
                 : "memory");
}

// ---------------- launch ----------------
extern "C" void kernel_launch(void* const* d_in, const int* in_sizes, int n_in,
                              void* d_out, int out_size) {
    const float* x_a   = (const float*)d_in[0];
    const float* x_b   = (const float*)d_in[1];
    const void*  ei_ab = d_in[2];
    const void*  ei_ba = d_in[3];
    const void*  ei_aa = d_in[4];
    const float* Wr1   = (const float*)d_in[5];
    const float* Wo1   = (const float*)d_in[6];
    const float* b1    = (const float*)d_in[7];
    const float* Wr2   = (const float*)d_in[8];
    const float* Wo2   = (const float*)d_in[9];
    const float* b2    = (const float*)d_in[10];
    float* out = (float*)d_out;

    probe_kernel<<<1, 256>>>((const unsigned*)ei_ab);

    zero_aggs<<<(N_A + 255) / 256, 256>>>();

    l1_edge<<<(3 * NE + 255) / 256, 256>>>(ei_ab, ei_ba, ei_aa, x_a, x_b);

    node_a<<<(N_A + 64 * RN - 1) / (64 * RN), 192>>>(x_a, Wr1, Wo1, b1, Wr2, Wo2, b2, out);
    node_b<<<(N_B + 64 * RN - 1) / (64 * RN), 128>>>(x_b, Wr1, Wo1, b1, Wr2, Wo2, b2, out);

    long long l2_items = 3LL * NE * 8;
    int l2_blocks = (int)((l2_items + 255) / 256);
    l2_edge<<<l2_blocks, 256>>>(ei_ab, ei_ba, ei_aa, out);
}

// round 14
// speedup vs baseline: 1.6665x; 1.6665x over previous
#include <cuda_runtime.h>
#include <stdint.h>

// Problem constants (fixed shapes)
#define N_A   500000
#define N_B   500000
#define NE    1000000
#define HID   64
#define NOUT  32

// ---------------- scratch (device globals: allocation-free) ----------------
__device__ float g_agg_ab[N_B];            // layer-1 scalar aggregates
__device__ float g_agg_ba[N_A];
__device__ float g_agg_aa[N_A];
__device__ float g_ta_ab[(size_t)N_A * NOUT];   // ha @ Wrel2[0]  (src-transform for a->b)
__device__ float g_ta_aa[(size_t)N_A * NOUT];   // ha @ Wrel2[2]  (src-transform for a->a)
__device__ float g_tb_ba[(size_t)N_B * NOUT];   // hb @ Wrel2[1]  (src-transform for b->a)
__device__ int   g_is64;                   // edge-index dtype flag

// ---------------- dtype probe ----------------
// int64 little-endian indices < 2^31 => every odd 32-bit word is 0.
__global__ void probe_kernel(const unsigned* __restrict__ ei) {
    __shared__ unsigned s;
    if (threadIdx.x == 0) s = 0u;
    __syncthreads();
    unsigned v = 0u;
    for (int i = threadIdx.x; i < 2048; i += blockDim.x) v |= ei[2 * i + 1];
    atomicOr(&s, v);
    __syncthreads();
    if (threadIdx.x == 0) g_is64 = (s == 0u) ? 1 : 0;
}

__device__ __forceinline__ int ld_idx(const void* __restrict__ ei, int row, int i, int is64) {
    if (is64) return (int)((const unsigned*)ei)[(((size_t)row * NE) + i) * 2];   // low word
    return ((const int*)ei)[((size_t)row * NE) + i];
}

// paired index load for even e: elements e and e+1 of row in one vector load
__device__ __forceinline__ void ld_idx2(const void* __restrict__ ei, int row, int e,
                                        int is64, int& i0, int& i1) {
    if (is64) {
        ulonglong2 v = ((const ulonglong2*)ei)[((size_t)row * NE + e) >> 1];
        i0 = (int)v.x; i1 = (int)v.y;
    } else {
        int2 v = ((const int2*)ei)[((size_t)row * NE + e) >> 1];
        i0 = v.x; i1 = v.y;
    }
}

// ---------------- zero the scalar aggregates (needed every replay) ----------------
__global__ void zero_aggs() {
    int gid = blockIdx.x * blockDim.x + threadIdx.x;
    if (gid < N_B) g_agg_ab[gid] = 0.f;
    if (gid < N_A) { g_agg_ba[gid] = 0.f; g_agg_aa[gid] = 0.f; }
}

// ---------------- layer-1 edge kernel: scalar scatter-add, 2 edges/thread ----------------
__global__ void l1_edge(const void* __restrict__ ei_ab,
                        const void* __restrict__ ei_ba,
                        const void* __restrict__ ei_aa,
                        const float* __restrict__ xa,
                        const float* __restrict__ xb) {
    int gid = blockIdx.x * blockDim.x + threadIdx.x;
    if (gid >= 3 * (NE / 2)) return;
    int is64 = g_is64;
    int t = gid / (NE / 2);
    int e = (gid - t * (NE / 2)) * 2;

    const void* ei = (t == 0) ? ei_ab : ((t == 1) ? ei_ba : ei_aa);
    const float* xs = (t == 1) ? xb : xa;
    float* agg = (t == 0) ? g_agg_ab : ((t == 1) ? g_agg_ba : g_agg_aa);

    int s0, s1, d0, d1;
    ld_idx2(ei, 0, e, is64, s0, s1);
    ld_idx2(ei, 1, e, is64, d0, d1);
    atomicAdd(&agg[d0], xs[s0]);
    atomicAdd(&agg[d1], xs[s1]);
}

// ---------------- packed f32x2 helpers ----------------
__device__ __forceinline__ unsigned long long pack2(float h) {
    unsigned long long r;
    asm("mov.b64 %0, {%1, %1};" : "=l"(r) : "f"(h));
    return r;
}
#define FMA2(acc, w, h) \
    asm("fma.rn.f32x2 %0, %1, %2, %0;" : "+l"(acc) : "l"(w), "l"(h))

#define RN 4   // nodes per thread

// ================= node kernel for 'a' nodes (R9 known-good) =================
// 3 thread-groups (q) own 32 output cols each: q=0 -> g_ta_ab, q=1 -> g_ta_aa,
// q=2 -> out(+bias). RN=4 nodes/thread so one weight-row LDS batch feeds 4x
// the FMA2 work (latency hiding via 64 indep accumulators).
__global__ void __launch_bounds__(192)
node_a(const float* __restrict__ xa,
       const float* __restrict__ Wr1, const float* __restrict__ Wo1,
       const float* __restrict__ b1,
       const float* __restrict__ Wr2, const float* __restrict__ Wo2,
       const float* __restrict__ b2,
       float* __restrict__ out) {
    __shared__ __align__(16) float  sW[HID * 96];   // 24 KB concatenated weights
    __shared__ __align__(16) float4 sH[HID];        // {u, v, w, c} per k
    __shared__ __align__(16) float  sbias[NOUT];

    int tid = threadIdx.x;
    for (int idx = tid; idx < HID * 96; idx += blockDim.x) {
        int k = idx / 96, j = idx - k * 96;
        float v;
        if (j < 32)       v = Wr2[0 * HID * NOUT + k * NOUT + j];
        else if (j < 64)  v = Wr2[2 * HID * NOUT + k * NOUT + (j - 32)];
        else              v = Wo2[1 * HID * NOUT + k * NOUT + (j - 64)]
                            + Wo2[2 * HID * NOUT + k * NOUT + (j - 64)];
        sW[idx] = v;
    }
    for (int k = tid; k < HID; k += blockDim.x) {
        sH[k] = make_float4(Wr1[1 * HID + k],
                            Wr1[2 * HID + k],
                            Wo1[1 * HID + k] + Wo1[2 * HID + k],
                            b1[1 * HID + k] + b1[2 * HID + k]);
    }
    for (int j = tid; j < NOUT; j += blockDim.x)
        sbias[j] = b2[1 * NOUT + j] + b2[2 * NOUT + j];
    __syncthreads();

    int q  = tid >> 6;         // 0,1,2 : column slice / destination
    int ln = tid & 63;         // lane-group index
    int base = blockIdx.x * (64 * RN) + ln;

    int   nn[RN];
    float s1[RN], s2[RN], s3[RN];
#pragma unroll
    for (int i = 0; i < RN; i++) {
        int n = base + i * 64;
        nn[i] = n;
        bool ok = (n < N_A);
        int nc = ok ? n : 0;
        s1[i] = ok ? g_agg_ba[nc] : 0.f;
        s2[i] = ok ? g_agg_aa[nc] : 0.f;
        s3[i] = ok ? xa[nc] : 0.f;
    }

    unsigned long long acc[RN][16];
#pragma unroll
    for (int i = 0; i < RN; i++) {
        if (q == 2) {
            const unsigned long long* pb = (const unsigned long long*)sbias;
#pragma unroll
            for (int j = 0; j < 16; j++) acc[i][j] = pb[j];
        } else {
#pragma unroll
            for (int j = 0; j < 16; j++) acc[i][j] = 0ULL;
        }
    }

    const ulonglong2* wptr = (const ulonglong2*)((const char*)sW + q * 32 * sizeof(float));
#pragma unroll 1
    for (int k = 0; k < HID; k++) {
        float4 hq = sH[k];
        unsigned long long hh[RN];
#pragma unroll
        for (int i = 0; i < RN; i++) {
            float h = fmaxf(fmaf(s1[i], hq.x, fmaf(s2[i], hq.y, fmaf(s3[i], hq.z, hq.w))), 0.f);
            hh[i] = pack2(h);
        }
#pragma unroll
        for (int m = 0; m < 8; m++) {
            ulonglong2 wv = wptr[m];
#pragma unroll
            for (int i = 0; i < RN; i++) {
                FMA2(acc[i][2 * m],     wv.x, hh[i]);
                FMA2(acc[i][2 * m + 1], wv.y, hh[i]);
            }
        }
        wptr += 24;   // advance one 96-float row (96*4B / 16B = 24 ulonglong2)
    }

    float* dst = (q == 0) ? g_ta_ab : (q == 1) ? g_ta_aa : out;
#pragma unroll
    for (int i = 0; i < RN; i++) {
        if (nn[i] < N_A) {
            ulonglong2* o = (ulonglong2*)(dst + (size_t)nn[i] * NOUT);
#pragma unroll
            for (int m = 0; m < 8; m++)
                o[m] = make_ulonglong2(acc[i][2 * m], acc[i][2 * m + 1]);
        }
    }
}

// ================= node kernel for 'b' nodes (R9 known-good) =================
// 2 thread-groups: q=0 -> g_tb_ba; q=1 -> out(+bias). RN=4 nodes per thread.
__global__ void __launch_bounds__(256)
node_b(const float* __restrict__ xb,
       const float* __restrict__ Wr1, const float* __restrict__ Wo1,
       const float* __restrict__ b1,
       const float* __restrict__ Wr2, const float* __restrict__ Wo2,
       const float* __restrict__ b2,
       float* __restrict__ out) {
    __shared__ __align__(16) float  sW[HID * 64];   // 16 KB
    __shared__ __align__(16) float4 sH[HID];        // {u, w, c, 0}
    __shared__ __align__(16) float  sbias[NOUT];

    int tid = threadIdx.x;
    for (int idx = tid; idx < HID * 64; idx += blockDim.x) {
        int k = idx / 64, j = idx - k * 64;
        float v;
        if (j < 32) v = Wr2[1 * HID * NOUT + k * NOUT + j];
        else        v = Wo2[0 * HID * NOUT + k * NOUT + (j - 32)];
        sW[idx] = v;
    }
    for (int k = tid; k < HID; k += blockDim.x) {
        sH[k] = make_float4(Wr1[0 * HID + k],
                            Wo1[0 * HID + k],
                            b1[0 * HID + k],
                            0.f);
    }
    for (int j = tid; j < NOUT; j += blockDim.x) sbias[j] = b2[0 * NOUT + j];
    __syncthreads();

    int q  = tid >> 7;         // 0,1 : column slice / destination
    int ln = tid & 127;        // lane-group index
    int base = blockIdx.x * (128 * RN) + ln;

    int   nn[RN];
    float s1[RN], s3[RN];
#pragma unroll
    for (int i = 0; i < RN; i++) {
        int n = base + i * 128;
        nn[i] = n;
        bool ok = (n < N_B);
        int nc = ok ? n : 0;
        s1[i] = ok ? g_agg_ab[nc] : 0.f;
        s3[i] = ok ? xb[nc] : 0.f;
    }

    unsigned long long acc[RN][16];
#pragma unroll
    for (int i = 0; i < RN; i++) {
        if (q == 1) {
            const unsigned long long* pb = (const unsigned long long*)sbias;
#pragma unroll
            for (int j = 0; j < 16; j++) acc[i][j] = pb[j];
        } else {
#pragma unroll
            for (int j = 0; j < 16; j++) acc[i][j] = 0ULL;
        }
    }

    const ulonglong2* wptr = (const ulonglong2*)((const char*)sW + q * 32 * sizeof(float));
#pragma unroll 1
    for (int k = 0; k < HID; k++) {
        float4 hq = sH[k];
        unsigned long long hh[RN];
#pragma unroll
        for (int i = 0; i < RN; i++) {
            float h = fmaxf(fmaf(s1[i], hq.x, fmaf(s3[i], hq.y, hq.z)), 0.f);
            hh[i] = pack2(h);
        }
#pragma unroll
        for (int m = 0; m < 8; m++) {
            ulonglong2 wv = wptr[m];
#pragma unroll
            for (int i = 0; i < RN; i++) {
                FMA2(acc[i][2 * m],     wv.x, hh[i]);
                FMA2(acc[i][2 * m + 1], wv.y, hh[i]);
            }
        }
        wptr += 16;   // advance one 64-float row (64*4B / 16B = 16 ulonglong2)
    }

    float* dst = (q == 0) ? g_tb_ba : (out + (size_t)N_A * NOUT);
#pragma unroll
    for (int i = 0; i < RN; i++) {
        if (nn[i] < N_B) {
            ulonglong2* o = (ulonglong2*)(dst + (size_t)nn[i] * NOUT);
#pragma unroll
            for (int m = 0; m < 8; m++)
                o[m] = make_ulonglong2(acc[i][2 * m], acc[i][2 * m + 1]);
        }
    }
}

// ---------------- layer-2 edge kernel: 4 threads/edge, 2x red.v4 each ----------------
// Halves redundant (s,d) index loads vs 8 threads/edge; same reduction bytes.
__global__ void l2_edge(const void* __restrict__ ei_ab,
                        const void* __restrict__ ei_ba,
                        const void* __restrict__ ei_aa,
                        float* __restrict__ out) {
    long long gid = (long long)blockIdx.x * blockDim.x + threadIdx.x;
    if (gid >= 3LL * NE * 4) return;
    int is64 = g_is64;
    int t = (int)(gid / (NE * 4LL));
    long long r = gid - (long long)t * (NE * 4LL);
    int e = (int)(r >> 2);
    int q = (int)(r & 3);

    const void* ei = (t == 0) ? ei_ab : ((t == 1) ? ei_ba : ei_aa);
    int s = ld_idx(ei, 0, e, is64);
    int d = ld_idx(ei, 1, e, is64);

    const float* tsrc = (t == 0) ? g_ta_ab : ((t == 1) ? g_tb_ba : g_ta_aa);
    size_t drow = (t == 0) ? (size_t)(N_A + d) : (size_t)d;   // ab edges land in b-rows

    const float* src = tsrc + (size_t)s * NOUT + q * 8;
    float4 v0 = *(const float4*)(src);
    float4 v1 = *(const float4*)(src + 4);
    float* p = out + drow * NOUT + q * 8;
    asm volatile("red.global.add.v4.f32 [%0], {%1, %2, %3, %4};"
                 :: "l"(p), "f"(v0.x), "f"(v0.y), "f"(v0.z), "f"(v0.w)
                 : "memory");
    asm volatile("red.global.add.v4.f32 [%0], {%1, %2, %3, %4};"
                 :: "l"(p + 4), "f"(v1.x), "f"(v1.y), "f"(v1.z), "f"(v1.w)
                 : "memory");
}

// ---------------- launch ----------------
extern "C" void kernel_launch(void* const* d_in, const int* in_sizes, int n_in,
                              void* d_out, int out_size) {
    const float* x_a   = (const float*)d_in[0];
    const float* x_b   = (const float*)d_in[1];
    const void*  ei_ab = d_in[2];
    const void*  ei_ba = d_in[3];
    const void*  ei_aa = d_in[4];
    const float* Wr1   = (const float*)d_in[5];
    const float* Wo1   = (const float*)d_in[6];
    const float* b1    = (const float*)d_in[7];
    const float* Wr2   = (const float*)d_in[8];
    const float* Wo2   = (const float*)d_in[9];
    const float* b2    = (const float*)d_in[10];
    float* out = (float*)d_out;

    probe_kernel<<<1, 256>>>((const unsigned*)ei_ab);

    zero_aggs<<<(N_A + 255) / 256, 256>>>();

    int l1_items = 3 * (NE / 2);
    l1_edge<<<(l1_items + 255) / 256, 256>>>(ei_ab, ei_ba, ei_aa, x_a, x_b);

    node_a<<<(N_A + 64 * RN - 1) / (64 * RN), 192>>>(x_a, Wr1, Wo1, b1, Wr2, Wo2, b2, out);
    node_b<<<(N_B + 128 * RN - 1) / (128 * RN), 256>>>(x_b, Wr1, Wo1, b1, Wr2, Wo2, b2, out);

    long long l2_items = 3LL * NE * 4;
    int l2_blocks = (int)((l2_items + 255) / 256);
    l2_edge<<<l2_blocks, 256>>>(ei_ab, ei_ba, ei_aa, out);
}

// round 16
// speedup vs baseline: 1.7432x; 1.0460x over previous
#include <cuda_runtime.h>
#include <stdint.h>

// Problem constants (fixed shapes)
#define N_A   500000
#define N_B   500000
#define NE    1000000
#define HID   64
#define NOUT  32

// ---------------- scratch (device globals: allocation-free) ----------------
__device__ float g_agg_ab[N_B];            // layer-1 scalar aggregates
__device__ float g_agg_ba[N_A];
__device__ float g_agg_aa[N_A];
__device__ float g_ta_ab[(size_t)N_A * NOUT];   // ha @ Wrel2[0]
__device__ float g_ta_aa[(size_t)N_A * NOUT];   // ha @ Wrel2[2]
__device__ float g_tb_ba[(size_t)N_B * NOUT];   // hb @ Wrel2[1]
__device__ int   g_is64;                   // edge-index dtype flag

// ---------------- dtype probe ----------------
__global__ void probe_kernel(const unsigned* __restrict__ ei) {
    __shared__ unsigned s;
    if (threadIdx.x == 0) s = 0u;
    __syncthreads();
    unsigned v = 0u;
    for (int i = threadIdx.x; i < 2048; i += blockDim.x) v |= ei[2 * i + 1];
    atomicOr(&s, v);
    __syncthreads();
    if (threadIdx.x == 0) g_is64 = (s == 0u) ? 1 : 0;
}

__device__ __forceinline__ int ld_idx(const void* __restrict__ ei, int row, int i, int is64) {
    if (is64) return (int)((const unsigned*)ei)[(((size_t)row * NE) + i) * 2];   // low word
    return ((const int*)ei)[((size_t)row * NE) + i];
}

// paired index load for even e: elements e and e+1 of row in one vector load
__device__ __forceinline__ void ld_idx2(const void* __restrict__ ei, int row, int e,
                                        int is64, int& i0, int& i1) {
    if (is64) {
        ulonglong2 v = ((const ulonglong2*)ei)[((size_t)row * NE + e) >> 1];
        i0 = (int)v.x; i1 = (int)v.y;
    } else {
        int2 v = ((const int2*)ei)[((size_t)row * NE + e) >> 1];
        i0 = v.x; i1 = v.y;
    }
}

// ---------------- zero the scalar aggregates ----------------
__global__ void zero_aggs() {
    int gid = blockIdx.x * blockDim.x + threadIdx.x;
    if (gid < N_B) g_agg_ab[gid] = 0.f;
    if (gid < N_A) { g_agg_ba[gid] = 0.f; g_agg_aa[gid] = 0.f; }
}

// ---------------- layer-1 edge kernel: scalar scatter-add, 2 edges/thread ----------------
__global__ void l1_edge(const void* __restrict__ ei_ab,
                        const void* __restrict__ ei_ba,
                        const void* __restrict__ ei_aa,
                        const float* __restrict__ xa,
                        const float* __restrict__ xb) {
    int gid = blockIdx.x * blockDim.x + threadIdx.x;
    if (gid >= 3 * (NE / 2)) return;
    int is64 = g_is64;
    int t = gid / (NE / 2);
    int e = (gid - t * (NE / 2)) * 2;

    const void* ei = (t == 0) ? ei_ab : ((t == 1) ? ei_ba : ei_aa);
    const float* xs = (t == 1) ? xb : xa;
    float* agg = (t == 0) ? g_agg_ab : ((t == 1) ? g_agg_ba : g_agg_aa);

    int s0, s1, d0, d1;
    ld_idx2(ei, 0, e, is64, s0, s1);
    ld_idx2(ei, 1, e, is64, d0, d1);
    atomicAdd(&agg[d0], xs[s0]);
    atomicAdd(&agg[d1], xs[s1]);
}

// ---------------- packed f32x2 helpers ----------------
__device__ __forceinline__ unsigned long long pack2(float h) {
    unsigned long long r;
    asm("mov.b64 %0, {%1, %1};" : "=l"(r) : "f"(h));
    return r;
}
#define FMA2(acc, w, h) \
    asm("fma.rn.f32x2 %0, %1, %2, %0;" : "+l"(acc) : "l"(w), "l"(h))

#define RN 4   // nodes per thread

// ================= node kernel for 'a' nodes (R14 known-good) =================
// 3 thread-groups (q) own 32 output cols each: q=0 -> g_ta_ab, q=1 -> g_ta_aa,
// q=2 -> out(+bias). RN=4 nodes/thread so one weight-row LDS batch feeds 4x
// the FMA2 work (latency hiding via 64 indep accumulators).
__global__ void __launch_bounds__(192)
node_a(const float* __restrict__ xa,
       const float* __restrict__ Wr1, const float* __restrict__ Wo1,
       const float* __restrict__ b1,
       const float* __restrict__ Wr2, const float* __restrict__ Wo2,
       const float* __restrict__ b2,
       float* __restrict__ out) {
    __shared__ __align__(16) float  sW[HID * 96];   // 24 KB concatenated weights
    __shared__ __align__(16) float4 sH[HID];        // {u, v, w, c} per k
    __shared__ __align__(16) float  sbias[NOUT];

    int tid = threadIdx.x;
    for (int idx = tid; idx < HID * 96; idx += blockDim.x) {
        int k = idx / 96, j = idx - k * 96;
        float v;
        if (j < 32)       v = Wr2[0 * HID * NOUT + k * NOUT + j];
        else if (j < 64)  v = Wr2[2 * HID * NOUT + k * NOUT + (j - 32)];
        else              v = Wo2[1 * HID * NOUT + k * NOUT + (j - 64)]
                            + Wo2[2 * HID * NOUT + k * NOUT + (j - 64)];
        sW[idx] = v;
    }
    for (int k = tid; k < HID; k += blockDim.x) {
        sH[k] = make_float4(Wr1[1 * HID + k],
                            Wr1[2 * HID + k],
                            Wo1[1 * HID + k] + Wo1[2 * HID + k],
                            b1[1 * HID + k] + b1[2 * HID + k]);
    }
    for (int j = tid; j < NOUT; j += blockDim.x)
        sbias[j] = b2[1 * NOUT + j] + b2[2 * NOUT + j];
    __syncthreads();

    int q  = tid >> 6;         // 0,1,2 : column slice / destination
    int ln = tid & 63;         // lane-group index
    int base = blockIdx.x * (64 * RN) + ln;

    int   nn[RN];
    float s1[RN], s2[RN], s3[RN];
#pragma unroll
    for (int i = 0; i < RN; i++) {
        int n = base + i * 64;
        nn[i] = n;
        bool ok = (n < N_A);
        int nc = ok ? n : 0;
        s1[i] = ok ? g_agg_ba[nc] : 0.f;
        s2[i] = ok ? g_agg_aa[nc] : 0.f;
        s3[i] = ok ? xa[nc] : 0.f;
    }

    unsigned long long acc[RN][16];
#pragma unroll
    for (int i = 0; i < RN; i++) {
        if (q == 2) {
            const unsigned long long* pb = (const unsigned long long*)sbias;
#pragma unroll
            for (int j = 0; j < 16; j++) acc[i][j] = pb[j];
        } else {
#pragma unroll
            for (int j = 0; j < 16; j++) acc[i][j] = 0ULL;
        }
    }

    const ulonglong2* wptr = (const ulonglong2*)((const char*)sW + q * 32 * sizeof(float));
#pragma unroll 1
    for (int k = 0; k < HID; k++) {
        float4 hq = sH[k];
        unsigned long long hh[RN];
#pragma unroll
        for (int i = 0; i < RN; i++) {
            float h = fmaxf(fmaf(s1[i], hq.x, fmaf(s2[i], hq.y, fmaf(s3[i], hq.z, hq.w))), 0.f);
            hh[i] = pack2(h);
        }
#pragma unroll
        for (int m = 0; m < 8; m++) {
            ulonglong2 wv = wptr[m];
#pragma unroll
            for (int i = 0; i < RN; i++) {
                FMA2(acc[i][2 * m],     wv.x, hh[i]);
                FMA2(acc[i][2 * m + 1], wv.y, hh[i]);
            }
        }
        wptr += 24;   // advance one 96-float row (96*4B / 16B = 24 ulonglong2)
    }

    float* dst = (q == 0) ? g_ta_ab : (q == 1) ? g_ta_aa : out;
#pragma unroll
    for (int i = 0; i < RN; i++) {
        if (nn[i] < N_A) {
            ulonglong2* o = (ulonglong2*)(dst + (size_t)nn[i] * NOUT);
#pragma unroll
            for (int m = 0; m < 8; m++)
                o[m] = make_ulonglong2(acc[i][2 * m], acc[i][2 * m + 1]);
        }
    }
}

// ================= node kernel for 'b' nodes =================
// 192-thread blocks: 2 q-groups x 96 lanes (group 0 = warps 0-2, group 1 =
// warps 3-5; all warps q-uniform). q=0 -> g_tb_ba; q=1 -> out(+bias).
// RN=4 nodes/thread. 192 x ~168 regs = 2 blocks/SM = 12 warps, matching
// node_a's proven occupancy (vs 8 warps at the old 256-thread geometry).
__global__ void __launch_bounds__(192)
node_b(const float* __restrict__ xb,
       const float* __restrict__ Wr1, const float* __restrict__ Wo1,
       const float* __restrict__ b1,
       const float* __restrict__ Wr2, const float* __restrict__ Wo2,
       const float* __restrict__ b2,
       float* __restrict__ out) {
    __shared__ __align__(16) float  sW[HID * 64];   // 16 KB
    __shared__ __align__(16) float4 sH[HID];        // {u, w, c, 0}
    __shared__ __align__(16) float  sbias[NOUT];

    int tid = threadIdx.x;
    for (int idx = tid; idx < HID * 64; idx += blockDim.x) {
        int k = idx / 64, j = idx - k * 64;
        float v;
        if (j < 32) v = Wr2[1 * HID * NOUT + k * NOUT + j];
        else        v = Wo2[0 * HID * NOUT + k * NOUT + (j - 32)];
        sW[idx] = v;
    }
    for (int k = tid; k < HID; k += blockDim.x) {
        sH[k] = make_float4(Wr1[0 * HID + k],
                            Wo1[0 * HID + k],
                            b1[0 * HID + k],
                            0.f);
    }
    for (int j = tid; j < NOUT; j += blockDim.x) sbias[j] = b2[0 * NOUT + j];
    __syncthreads();

    int q  = (tid >= 96) ? 1 : 0;   // column slice / destination (warp-uniform)
    int ln = tid - q * 96;          // lane-group index 0..95
    int base = blockIdx.x * (96 * RN) + ln;

    int   nn[RN];
    float s1[RN], s3[RN];
#pragma unroll
    for (int i = 0; i < RN; i++) {
        int n = base + i * 96;
        nn[i] = n;
        bool ok = (n < N_B);
        int nc = ok ? n : 0;
        s1[i] = ok ? g_agg_ab[nc] : 0.f;
        s3[i] = ok ? xb[nc] : 0.f;
    }

    unsigned long long acc[RN][16];
#pragma unroll
    for (int i = 0; i < RN; i++) {
        if (q == 1) {
            const unsigned long long* pb = (const unsigned long long*)sbias;
#pragma unroll
            for (int j = 0; j < 16; j++) acc[i][j] = pb[j];
        } else {
#pragma unroll
            for (int j = 0; j < 16; j++) acc[i][j] = 0ULL;
        }
    }

    const ulonglong2* wptr = (const ulonglong2*)((const char*)sW + q * 32 * sizeof(float));
#pragma unroll 1
    for (int k = 0; k < HID; k++) {
        float4 hq = sH[k];
        unsigned long long hh[RN];
#pragma unroll
        for (int i = 0; i < RN; i++) {
            float h = fmaxf(fmaf(s1[i], hq.x, fmaf(s3[i], hq.y, hq.z)), 0.f);
            hh[i] = pack2(h);
        }
#pragma unroll
        for (int m = 0; m < 8; m++) {
            ulonglong2 wv = wptr[m];
#pragma unroll
            for (int i = 0; i < RN; i++) {
                FMA2(acc[i][2 * m],     wv.x, hh[i]);
                FMA2(acc[i][2 * m + 1], wv.y, hh[i]);
            }
        }
        wptr += 16;   // advance one 64-float row (64*4B / 16B = 16 ulonglong2)
    }

    float* dst = (q == 0) ? g_tb_ba : (out + (size_t)N_A * NOUT);
#pragma unroll
    for (int i = 0; i < RN; i++) {
        if (nn[i] < N_B) {
            ulonglong2* o = (ulonglong2*)(dst + (size_t)nn[i] * NOUT);
#pragma unroll
            for (int m = 0; m < 8; m++)
                o[m] = make_ulonglong2(acc[i][2 * m], acc[i][2 * m + 1]);
        }
    }
}

// ---------------- layer-2 edge kernel: 4 threads/edge, 2x red.v4 each ----------------
__global__ void l2_edge(const void* __restrict__ ei_ab,
                        const void* __restrict__ ei_ba,
                        const void* __restrict__ ei_aa,
                        float* __restrict__ out) {
    long long gid = (long long)blockIdx.x * blockDim.x + threadIdx.x;
    if (gid >= 3LL * NE * 4) return;
    int is64 = g_is64;
    int t = (int)(gid / (NE * 4LL));
    long long r = gid - (long long)t * (NE * 4LL);
    int e = (int)(r >> 2);
    int q = (int)(r & 3);

    const void* ei = (t == 0) ? ei_ab : ((t == 1) ? ei_ba : ei_aa);
    int s = ld_idx(ei, 0, e, is64);
    int d = ld_idx(ei, 1, e, is64);

    const float* tsrc = (t == 0) ? g_ta_ab : ((t == 1) ? g_tb_ba : g_ta_aa);
    size_t drow = (t == 0) ? (size_t)(N_A + d) : (size_t)d;   // ab edges land in b-rows

    const float* src = tsrc + (size_t)s * NOUT + q * 8;
    float4 v0 = *(const float4*)(src);
    float4 v1 = *(const float4*)(src + 4);
    float* p = out + drow * NOUT + q * 8;
    asm volatile("red.global.add.v4.f32 [%0], {%1, %2, %3, %4};"
                 :: "l"(p), "f"(v0.x), "f"(v0.y), "f"(v0.z), "f"(v0.w)
                 : "memory");
    asm volatile("red.global.add.v4.f32 [%0], {%1, %2, %3, %4};"
                 :: "l"(p + 4), "f"(v1.x), "f"(v1.y), "f"(v1.z), "f"(v1.w)
                 : "memory");
}

// ---------------- launch ----------------
extern "C" void kernel_launch(void* const* d_in, const int* in_sizes, int n_in,
                              void* d_out, int out_size) {
    const float* x_a   = (const float*)d_in[0];
    const float* x_b   = (const float*)d_in[1];
    const void*  ei_ab = d_in[2];
    const void*  ei_ba = d_in[3];
    const void*  ei_aa = d_in[4];
    const float* Wr1   = (const float*)d_in[5];
    const float* Wo1   = (const float*)d_in[6];
    const float* b1    = (const float*)d_in[7];
    const float* Wr2   = (const float*)d_in[8];
    const float* Wo2   = (const float*)d_in[9];
    const float* b2    = (const float*)d_in[10];
    float* out = (float*)d_out;

    probe_kernel<<<1, 256>>>((const unsigned*)ei_ab);

    zero_aggs<<<(N_A + 255) / 256, 256>>>();

    int l1_items = 3 * (NE / 2);
    l1_edge<<<(l1_items + 255) / 256, 256>>>(ei_ab, ei_ba, ei_aa, x_a, x_b);

    node_a<<<(N_A + 64 * RN - 1) / (64 * RN), 192>>>(x_a, Wr1, Wo1, b1, Wr2, Wo2, b2, out);
    node_b<<<(N_B + 96 * RN - 1) / (96 * RN), 192>>>(x_b, Wr1, Wo1, b1, Wr2, Wo2, b2, out);

    long long l2_items = 3LL * NE * 4;
    int l2_blocks = (int)((l2_items + 255) / 256);
    l2_edge<<<l2_blocks, 256>>>(ei_ab, ei_ba, ei_aa, out);
}